// round 5
// baseline (speedup 1.0000x reference)
#include <cuda_runtime.h>
#include <cuda_bf16.h>
#include <cstdint>

// Problem dims
#define BQ 64
#define LQ 256
#define DQ 1024
#define FQ 1024
#define MQ (BQ * LQ)    // 16384 GEMM rows
#define NQ (2 * FQ)     // 2048 interleaved: col 2f = X@W0[:,f] ("a"), col 2f+1 = X@W1[:,f] ("c")

// ---------------- scratch (device globals: no allocation allowed) ----------------
__device__ __align__(1024) __nv_bfloat16 g_Xb[MQ * DQ];   // X bf16 [M, D]
__device__ __align__(1024) __nv_bfloat16 g_Wt[NQ * DQ];   // interleaved [W0^T|W1^T] bf16 [2048, D]

// ---------------- helpers ----------------
__device__ __forceinline__ uint32_t smem_u32(const void* p) {
    uint32_t a;
    asm("{ .reg .u64 t; cvta.to.shared.u64 t, %1; cvt.u32.u64 %0, t; }" : "=r"(a) : "l"(p));
    return a;
}

#define CP_ASYNC16(dst_u32, src_ptr) \
    asm volatile("cp.async.cg.shared.global [%0], [%1], 16;" :: "r"(dst_u32), "l"(src_ptr))
#define CP_COMMIT() asm volatile("cp.async.commit_group;" ::: "memory")

#define SW128(off) ((off) ^ (((off) >> 3) & 0x70))

__device__ __forceinline__ void ldsm_x4(uint32_t* r, uint32_t addr) {
    asm volatile("ldmatrix.sync.aligned.m8n8.x4.shared.b16 {%0,%1,%2,%3}, [%4];"
                 : "=r"(r[0]), "=r"(r[1]), "=r"(r[2]), "=r"(r[3]) : "r"(addr));
}

__device__ __forceinline__ void mma16816(float* d, const uint32_t* a, const uint32_t* b) {
    asm volatile(
        "mma.sync.aligned.m16n8k16.row.col.f32.bf16.bf16.f32 "
        "{%0,%1,%2,%3}, {%4,%5,%6,%7}, {%8,%9}, {%0,%1,%2,%3};"
        : "+f"(d[0]), "+f"(d[1]), "+f"(d[2]), "+f"(d[3])
        : "r"(a[0]), "r"(a[1]), "r"(a[2]), "r"(a[3]), "r"(b[0]), "r"(b[1]));
}

// ---------------- GEMM config ----------------
#define TM 256                       // == LQ: one M-tile = one full batch sequence
#define TN 128                       // 64 interleaved (a,c) column pairs
#define KC 64                        // bf16 elems per K stage -> 128 B rows
#define NK (DQ / KC)                 // 16
#define A_ST (TM * 128)              // 32 KB
#define B_ST (TN * 128)              // 16 KB
#define STB (A_ST + B_ST)            // 48 KB
#define NSTG 4
#define SMEM_BYTES (NSTG * STB)      // 192 KB
// scan buffer reuses pipeline smem: float2 scanb[256][65] = 133,120 B
#define SCAN_STRIDE 65
#define SEGBUF_OFF (136 * 1024)      // 3 x 256 floats; well below 192 KB

#define NTHREADS 256                 // 8 warps, warp tile 64x64

// ---------------- convert kernels ----------------
__global__ void convert_x_kernel(const float4* __restrict__ in) {
    int i = blockIdx.x * blockDim.x + threadIdx.x;   // MQ*DQ/4 threads
    float4 v = in[i];
    __nv_bfloat162 h0, h1;
    h0.x = __float2bfloat16(v.x); h0.y = __float2bfloat16(v.y);
    h1.x = __float2bfloat16(v.z); h1.y = __float2bfloat16(v.w);
    __nv_bfloat162* out = reinterpret_cast<__nv_bfloat162*>(g_Xb);
    out[2 * i]     = h0;
    out[2 * i + 1] = h1;
}

// W[d, f] fp32 -> g_Wt[2f + z][d] bf16 (interleaved a/c rows)
__global__ void wtrans_kernel(const float* __restrict__ W0, const float* __restrict__ W1) {
    __shared__ float t[32][33];
    const float* W = blockIdx.z ? W1 : W0;
    int z = blockIdx.z;
    int f0 = blockIdx.x * 32;
    int d0 = blockIdx.y * 32;
    int tx = threadIdx.x, ty = threadIdx.y;   // 32 x 8
#pragma unroll
    for (int r = 0; r < 4; r++)
        t[ty + 8 * r][tx] = W[(size_t)(d0 + ty + 8 * r) * FQ + f0 + tx];
    __syncthreads();
#pragma unroll
    for (int r = 0; r < 4; r++)
        g_Wt[(size_t)(2 * (f0 + ty + 8 * r) + z) * DQ + d0 + tx] = __float2bfloat16(t[tx][ty + 8 * r]);
}

// ---------------- fused dual GEMM + recurrence + tanh ----------------
__device__ __forceinline__ void load_stage(uint32_t stage_base, const __nv_bfloat16* xg,
                                           const __nv_bfloat16* wg, int kc, int tid) {
    const __nv_bfloat16* xs = xg + kc * KC;
    const __nv_bfloat16* ws = wg + kc * KC;
    // A: 256 rows x 8 chunks of 16B = 2048 -> 8 per thread
#pragma unroll
    for (int i = 0; i < 8; i++) {
        int c = i * NTHREADS + tid;
        int r = c >> 3, j = c & 7;
        uint32_t off = (uint32_t)(r * 128 + j * 16);
        CP_ASYNC16(stage_base + SW128(off), xs + (size_t)r * DQ + j * 8);
    }
    // B: 128 rows x 8 chunks = 1024 -> 4 per thread
#pragma unroll
    for (int i = 0; i < 4; i++) {
        int c = i * NTHREADS + tid;
        int r = c >> 3, j = c & 7;
        uint32_t off = (uint32_t)(r * 128 + j * 16);
        CP_ASYNC16(stage_base + A_ST + SW128(off), ws + (size_t)r * DQ + j * 8);
    }
    CP_COMMIT();
}

__global__ void __launch_bounds__(NTHREADS, 1)
fused_gemm_scan_kernel(const float* __restrict__ bias, float* __restrict__ out) {
    extern __shared__ char smem[];
    uint32_t sbase = smem_u32(smem);
    int tid = threadIdx.x;
    int wid = tid >> 5, lane = tid & 31;
    int warp_m = wid & 3;     // 4 -> 64 rows each
    int warp_n = wid >> 2;    // 2 -> 64 cols each
    const int b  = blockIdx.x;            // batch == M-tile (256 rows)
    const int n0 = blockIdx.y * TN;       // interleaved col tile

    const __nv_bfloat16* xg = g_Xb + (size_t)(b * TM) * DQ;
    const __nv_bfloat16* wg = g_Wt + (size_t)n0 * DQ;

    float acc[4][8][4];
#pragma unroll
    for (int mi = 0; mi < 4; mi++)
#pragma unroll
        for (int ni = 0; ni < 8; ni++)
#pragma unroll
            for (int e = 0; e < 4; e++) acc[mi][ni][e] = 0.f;

    load_stage(sbase + 0 * STB, xg, wg, 0, tid);
    load_stage(sbase + 1 * STB, xg, wg, 1, tid);
    load_stage(sbase + 2 * STB, xg, wg, 2, tid);

    int lr = lane & 15;       // ldmatrix row-within-16
    int lc = lane >> 4;       // 16B column-half select

    for (int kc = 0; kc < NK; kc++) {
        if (kc < NK - 2)       asm volatile("cp.async.wait_group 2;" ::: "memory");
        else if (kc == NK - 2) asm volatile("cp.async.wait_group 1;" ::: "memory");
        else                   asm volatile("cp.async.wait_group 0;" ::: "memory");
        __syncthreads();

        if (kc + 3 < NK)
            load_stage(sbase + ((kc + 3) & 3) * STB, xg, wg, kc + 3, tid);

        uint32_t sa = sbase + (kc & 3) * STB;
        uint32_t sb = sa + A_ST;

#pragma unroll
        for (int k16 = 0; k16 < 4; k16++) {
            uint32_t av[4][4];
#pragma unroll
            for (int mi = 0; mi < 4; mi++) {
                int r = warp_m * 64 + mi * 16 + lr;
                uint32_t off = (uint32_t)(r * 128 + (k16 * 2 + lc) * 16);
                ldsm_x4(av[mi], sa + SW128(off));
            }
            uint32_t bv[4][4];
#pragma unroll
            for (int p = 0; p < 4; p++) {
                int r = warp_n * 64 + p * 16 + lr;
                uint32_t off = (uint32_t)(r * 128 + (k16 * 2 + lc) * 16);
                ldsm_x4(bv[p], sb + SW128(off));
            }
#pragma unroll
            for (int mi = 0; mi < 4; mi++) {
#pragma unroll
                for (int ni = 0; ni < 8; ni++) {
                    uint32_t b2[2] = { bv[ni >> 1][ni & 1], bv[ni >> 1][2 + (ni & 1)] };
                    mma16816(acc[mi][ni], av[mi], b2);
                }
            }
        }
    }

    // ---------- fused epilogue: segment-parallel max-recurrence + tanh ----------
    // acc col: c0 = warp_n*64 + ni*8 + (lane&3)*2 -> pair f = c0/2 = warp_n*32 + ni*4 + (lane&3)
    float2* scanb = reinterpret_cast<float2*>(smem);   // [256][SCAN_STRIDE]
#pragma unroll
    for (int mi = 0; mi < 4; mi++) {
        int r0 = warp_m * 64 + mi * 16 + (lane >> 2);
#pragma unroll
        for (int ni = 0; ni < 8; ni++) {
            int f = warp_n * 32 + ni * 4 + (lane & 3);
            scanb[r0 * SCAN_STRIDE + f]       = make_float2(acc[mi][ni][0], acc[mi][ni][1]);
            scanb[(r0 + 8) * SCAN_STRIDE + f] = make_float2(acc[mi][ni][2], acc[mi][ni][3]);
        }
    }
    __syncthreads();

    // per-segment summaries: 256 threads = 64 f x 4 segments of 64 steps
    float* segA = reinterpret_cast<float*>(smem + SEGBUF_OFF);
    float* segC = segA + 256;
    float* segH = segC + 256;
    {
        int f = tid & 63, s = tid >> 6;
        float P = -1e30f, C = -1e30f, H = -1e30f;
        const float2* col = scanb + (size_t)(s * 64) * SCAN_STRIDE + f;
#pragma unroll 4
        for (int l = 0; l < 64; l++) {
            float2 v = col[l * SCAN_STRIDE];
            H = fmaxf(H, P + v.y);   // uses prefix max of a BEFORE step l (matches ordering)
            C = fmaxf(C, v.y);
            P = fmaxf(P, v.x);
        }
        segA[s * 64 + f] = P;
        segC[s * 64 + f] = C;
        segH[s * 64 + f] = H;
    }
    __syncthreads();

    // combine 4 segments (init h1 = h2 = 0 per reference), tanh, store
    if (tid < 64) {
        float h2 = 0.f, m = 0.f;
#pragma unroll
        for (int s = 0; s < 4; s++) {
            h2 = fmaxf(h2, fmaxf(m + segC[s * 64 + tid], segH[s * 64 + tid]));
            m  = fmaxf(m, segA[s * 64 + tid]);
        }
        int fg = blockIdx.y * 64 + tid;
        out[b * FQ + fg] = tanhf(h2 + bias[fg]);
    }
}

// ---------------- launch ----------------
extern "C" void kernel_launch(void* const* d_in, const int* in_sizes, int n_in,
                              void* d_out, int out_size) {
    const float* x    = (const float*)d_in[0];   // [64, 256, 1024]
    const float* W0   = (const float*)d_in[1];   // [1024, 1024]
    const float* W1   = (const float*)d_in[2];   // [1024, 1024]
    const float* bias = (const float*)d_in[3];   // [1024]
    float* out        = (float*)d_out;           // [64, 1024]

    cudaFuncSetAttribute(fused_gemm_scan_kernel,
                         cudaFuncAttributeMaxDynamicSharedMemorySize, SMEM_BYTES);

    // 1) X -> bf16 (row m = b*256 + l matches flat input order)
    convert_x_kernel<<<(MQ * DQ / 4) / 256, 256>>>(reinterpret_cast<const float4*>(x));
    // 2) W0,W1 -> interleaved transposed bf16 [2048, 1024]
    wtrans_kernel<<<dim3(FQ / 32, DQ / 32, 2), dim3(32, 8)>>>(W0, W1);
    // 3) fused dual GEMM + recurrence + tanh
    fused_gemm_scan_kernel<<<dim3(BQ, NQ / TN), NTHREADS, SMEM_BYTES>>>(bias, out);
}

// round 6
// speedup vs baseline: 1.1126x; 1.1126x over previous
#include <cuda_runtime.h>
#include <cuda_bf16.h>
#include <cstdint>

// Problem dims
#define BQ 64
#define LQ 256
#define DQ 1024
#define FQ 1024
#define MQ (BQ * LQ)    // 16384 GEMM rows
#define NQ (2 * FQ)     // 2048 interleaved: col 2f = X@W0[:,f] ("a"), col 2f+1 = X@W1[:,f] ("c")

// ---------------- scratch (device globals: no allocation allowed) ----------------
__device__ __align__(1024) __nv_bfloat16 g_Xb[MQ * DQ];   // X bf16 [M, D]
__device__ __align__(1024) __nv_bfloat16 g_Wt[NQ * DQ];   // interleaved [W0^T|W1^T] bf16 [2048, D]

// ---------------- helpers ----------------
__device__ __forceinline__ uint32_t smem_u32(const void* p) {
    uint32_t a;
    asm("{ .reg .u64 t; cvta.to.shared.u64 t, %1; cvt.u32.u64 %0, t; }" : "=r"(a) : "l"(p));
    return a;
}

#define CP_ASYNC16(dst_u32, src_ptr) \
    asm volatile("cp.async.cg.shared.global [%0], [%1], 16;" :: "r"(dst_u32), "l"(src_ptr))
#define CP_COMMIT() asm volatile("cp.async.commit_group;" ::: "memory")

#define SW128(off) ((off) ^ (((off) >> 3) & 0x70))

__device__ __forceinline__ void ldsm_x4(uint32_t* r, uint32_t addr) {
    asm volatile("ldmatrix.sync.aligned.m8n8.x4.shared.b16 {%0,%1,%2,%3}, [%4];"
                 : "=r"(r[0]), "=r"(r[1]), "=r"(r[2]), "=r"(r[3]) : "r"(addr));
}

__device__ __forceinline__ void mma16816(float* d, const uint32_t* a, const uint32_t* b) {
    asm volatile(
        "mma.sync.aligned.m16n8k16.row.col.f32.bf16.bf16.f32 "
        "{%0,%1,%2,%3}, {%4,%5,%6,%7}, {%8,%9}, {%0,%1,%2,%3};"
        : "+f"(d[0]), "+f"(d[1]), "+f"(d[2]), "+f"(d[3])
        : "r"(a[0]), "r"(a[1]), "r"(a[2]), "r"(a[3]), "r"(b[0]), "r"(b[1]));
}

// ---------------- GEMM config ----------------
#define TM 256                       // == LQ: one M-tile = one full batch sequence
#define TN 64                        // 32 interleaved (a,c) column pairs
#define KC 64                        // bf16 elems per K stage -> 128 B rows
#define NK (DQ / KC)                 // 16
#define A_ST (TM * 128)              // 32 KB
#define B_ST (TN * 128)              // 8 KB
#define STB (A_ST + B_ST)            // 40 KB
#define NSTG 2
#define SMEM_BYTES (NSTG * STB)      // 80 KB -> 2 CTAs/SM
// epilogue reuses pipeline smem: uint32 (bf16x2) scanb[256][33] = 33.8 KB
#define SCAN_STRIDE 33
#define SEGBUF_OFF (35 * 1024)       // 3 x 256 floats = 3 KB, ends < 40 KB

#define NTHREADS 256                 // 8 warps, warp tile 64x32, 2 CTAs/SM

// ---------------- convert kernels ----------------
__global__ void convert_x_kernel(const float4* __restrict__ in) {
    int i = blockIdx.x * blockDim.x + threadIdx.x;   // MQ*DQ/4 threads
    float4 v = in[i];
    __nv_bfloat162 h0, h1;
    h0.x = __float2bfloat16(v.x); h0.y = __float2bfloat16(v.y);
    h1.x = __float2bfloat16(v.z); h1.y = __float2bfloat16(v.w);
    __nv_bfloat162* out = reinterpret_cast<__nv_bfloat162*>(g_Xb);
    out[2 * i]     = h0;
    out[2 * i + 1] = h1;
}

// W[d, f] fp32 -> g_Wt[2f + z][d] bf16 (interleaved a/c rows)
__global__ void wtrans_kernel(const float* __restrict__ W0, const float* __restrict__ W1) {
    __shared__ float t[32][33];
    const float* W = blockIdx.z ? W1 : W0;
    int z = blockIdx.z;
    int f0 = blockIdx.x * 32;
    int d0 = blockIdx.y * 32;
    int tx = threadIdx.x, ty = threadIdx.y;   // 32 x 8
#pragma unroll
    for (int r = 0; r < 4; r++)
        t[ty + 8 * r][tx] = W[(size_t)(d0 + ty + 8 * r) * FQ + f0 + tx];
    __syncthreads();
#pragma unroll
    for (int r = 0; r < 4; r++)
        g_Wt[(size_t)(2 * (f0 + ty + 8 * r) + z) * DQ + d0 + tx] = __float2bfloat16(t[tx][ty + 8 * r]);
}

// ---------------- fused dual GEMM + recurrence + tanh ----------------
__device__ __forceinline__ void load_stage(uint32_t stage_base, const __nv_bfloat16* xg,
                                           const __nv_bfloat16* wg, int kc, int tid) {
    const __nv_bfloat16* xs = xg + kc * KC;
    const __nv_bfloat16* ws = wg + kc * KC;
    // A: 256 rows x 8 chunks of 16B = 2048 -> 8 per thread
#pragma unroll
    for (int i = 0; i < 8; i++) {
        int c = i * NTHREADS + tid;
        int r = c >> 3, j = c & 7;
        uint32_t off = (uint32_t)(r * 128 + j * 16);
        CP_ASYNC16(stage_base + SW128(off), xs + (size_t)r * DQ + j * 8);
    }
    // B: 64 rows x 8 chunks = 512 -> 2 per thread
#pragma unroll
    for (int i = 0; i < 2; i++) {
        int c = i * NTHREADS + tid;
        int r = c >> 3, j = c & 7;
        uint32_t off = (uint32_t)(r * 128 + j * 16);
        CP_ASYNC16(stage_base + A_ST + SW128(off), ws + (size_t)r * DQ + j * 8);
    }
    CP_COMMIT();
}

__global__ void __launch_bounds__(NTHREADS, 2)
fused_gemm_scan_kernel(const float* __restrict__ bias, float* __restrict__ out) {
    extern __shared__ char smem[];
    uint32_t sbase = smem_u32(smem);
    int tid = threadIdx.x;
    int wid = tid >> 5, lane = tid & 31;
    int warp_m = wid & 3;     // 4 -> 64 rows each
    int warp_n = wid >> 2;    // 2 -> 32 cols each
    const int b  = blockIdx.x;            // batch == M-tile (256 rows)
    const int n0 = blockIdx.y * TN;       // interleaved col tile

    const __nv_bfloat16* xg = g_Xb + (size_t)(b * TM) * DQ;
    const __nv_bfloat16* wg = g_Wt + (size_t)n0 * DQ;

    float acc[4][4][4];
#pragma unroll
    for (int mi = 0; mi < 4; mi++)
#pragma unroll
        for (int ni = 0; ni < 4; ni++)
#pragma unroll
            for (int e = 0; e < 4; e++) acc[mi][ni][e] = 0.f;

    load_stage(sbase, xg, wg, 0, tid);

    int lr = lane & 15;       // ldmatrix row-within-16
    int lc = lane >> 4;       // 16B column-half select

    for (int kc = 0; kc < NK; kc++) {
        asm volatile("cp.async.wait_group 0;" ::: "memory");
        __syncthreads();      // all warps: stage kc ready AND done reading stage kc-1

        if (kc + 1 < NK)
            load_stage(sbase + ((kc + 1) & 1) * STB, xg, wg, kc + 1, tid);   // overlaps compute

        uint32_t sa = sbase + (kc & 1) * STB;
        uint32_t sb = sa + A_ST;

#pragma unroll
        for (int k16 = 0; k16 < 4; k16++) {
            uint32_t av[4][4];
#pragma unroll
            for (int mi = 0; mi < 4; mi++) {
                int r = warp_m * 64 + mi * 16 + lr;
                uint32_t off = (uint32_t)(r * 128 + (k16 * 2 + lc) * 16);
                ldsm_x4(av[mi], sa + SW128(off));
            }
            uint32_t bv[2][4];
#pragma unroll
            for (int p = 0; p < 2; p++) {
                int r = warp_n * 32 + p * 16 + lr;
                uint32_t off = (uint32_t)(r * 128 + (k16 * 2 + lc) * 16);
                ldsm_x4(bv[p], sb + SW128(off));
            }
#pragma unroll
            for (int mi = 0; mi < 4; mi++) {
#pragma unroll
                for (int ni = 0; ni < 4; ni++) {
                    uint32_t b2[2] = { bv[ni >> 1][ni & 1], bv[ni >> 1][2 + (ni & 1)] };
                    mma16816(acc[mi][ni], av[mi], b2);
                }
            }
        }
    }

    // ---------- fused epilogue: segment-parallel max-recurrence + tanh ----------
    // acc col: c0 = warp_n*32 + ni*8 + (lane&3)*2 -> pair f = warp_n*16 + ni*4 + (lane&3)
    __syncthreads();   // mainloop fully done before smem reuse
    uint32_t* scanb = reinterpret_cast<uint32_t*>(smem);   // [256][SCAN_STRIDE] bf16x2(a,c)
#pragma unroll
    for (int mi = 0; mi < 4; mi++) {
        int r0 = warp_m * 64 + mi * 16 + (lane >> 2);
#pragma unroll
        for (int ni = 0; ni < 4; ni++) {
            int f = warp_n * 16 + ni * 4 + (lane & 3);
            __nv_bfloat162 h0, h1;
            h0.x = __float2bfloat16(acc[mi][ni][0]);   // a at row r0
            h0.y = __float2bfloat16(acc[mi][ni][1]);   // c at row r0
            h1.x = __float2bfloat16(acc[mi][ni][2]);   // a at row r0+8
            h1.y = __float2bfloat16(acc[mi][ni][3]);   // c at row r0+8
            scanb[r0 * SCAN_STRIDE + f]       = *reinterpret_cast<uint32_t*>(&h0);
            scanb[(r0 + 8) * SCAN_STRIDE + f] = *reinterpret_cast<uint32_t*>(&h1);
        }
    }
    __syncthreads();

    // per-segment summaries: 256 threads = 32 f x 8 segments of 32 steps
    float* segA = reinterpret_cast<float*>(smem + SEGBUF_OFF);
    float* segC = segA + 256;
    float* segH = segC + 256;
    {
        int f = tid & 31, s = tid >> 5;
        float P = -1e30f, C = -1e30f, H = -1e30f;
        const uint32_t* col = scanb + (size_t)(s * 32) * SCAN_STRIDE + f;
#pragma unroll 4
        for (int l = 0; l < 32; l++) {
            uint32_t u = col[l * SCAN_STRIDE];
            __nv_bfloat162 v = *reinterpret_cast<__nv_bfloat162*>(&u);
            float a = __bfloat162float(v.x), c = __bfloat162float(v.y);
            H = fmaxf(H, P + c);   // prefix max of a BEFORE step l (matches ordering)
            C = fmaxf(C, c);
            P = fmaxf(P, a);
        }
        segA[s * 32 + f] = P;
        segC[s * 32 + f] = C;
        segH[s * 32 + f] = H;
    }
    __syncthreads();

    // combine 8 segments (init h1 = h2 = 0 per reference), tanh, store
    if (tid < 32) {
        float h2 = 0.f, m = 0.f;
#pragma unroll
        for (int s = 0; s < 8; s++) {
            h2 = fmaxf(h2, fmaxf(m + segC[s * 32 + tid], segH[s * 32 + tid]));
            m  = fmaxf(m, segA[s * 32 + tid]);
        }
        int fg = blockIdx.y * 32 + tid;
        out[b * FQ + fg] = tanhf(h2 + bias[fg]);
    }
}

// ---------------- launch ----------------
extern "C" void kernel_launch(void* const* d_in, const int* in_sizes, int n_in,
                              void* d_out, int out_size) {
    const float* x    = (const float*)d_in[0];   // [64, 256, 1024]
    const float* W0   = (const float*)d_in[1];   // [1024, 1024]
    const float* W1   = (const float*)d_in[2];   // [1024, 1024]
    const float* bias = (const float*)d_in[3];   // [1024]
    float* out        = (float*)d_out;           // [64, 1024]

    cudaFuncSetAttribute(fused_gemm_scan_kernel,
                         cudaFuncAttributeMaxDynamicSharedMemorySize, SMEM_BYTES);

    // NOTE: wtrans launched FIRST (capture-mapping diagnostic: ncu seems to profile
    // the first launch of an invocation; if next profile shows wtrans, confirmed).
    // 1) W0,W1 -> interleaved transposed bf16 [2048, 1024]
    wtrans_kernel<<<dim3(FQ / 32, DQ / 32, 2), dim3(32, 8)>>>(W0, W1);
    // 2) X -> bf16 (row m = b*256 + l matches flat input order)
    convert_x_kernel<<<(MQ * DQ / 4) / 256, 256>>>(reinterpret_cast<const float4*>(x));
    // 3) fused dual GEMM + recurrence + tanh (2 CTAs/SM)
    fused_gemm_scan_kernel<<<dim3(BQ, NQ / TN), NTHREADS, SMEM_BYTES>>>(bias, out);
}